// round 16
// baseline (speedup 1.0000x reference)
#include <cuda_runtime.h>
#include <cuda_fp16.h>
#include <math.h>
#include <stdint.h>

#define B_ 16
#define N_ 2048
#define D_ 64

typedef unsigned int u32;

// ---------------------------- helpers ---------------------------------------
__device__ __forceinline__ u32 smem_u32(const void* p) {
    u32 a;
    asm("{ .reg .u64 t; cvta.to.shared.u64 t, %1; cvt.u32.u64 %0, t; }"
        : "=r"(a) : "l"(p));
    return a;
}
__device__ __forceinline__ void ldm4(u32* r, u32 a) {
    asm volatile("ldmatrix.sync.aligned.m8n8.x4.shared.b16 {%0,%1,%2,%3}, [%4];"
        : "=r"(r[0]), "=r"(r[1]), "=r"(r[2]), "=r"(r[3]) : "r"(a));
}
__device__ __forceinline__ void mma_f16(float* c, const u32* a, u32 b0, u32 b1) {
    asm volatile("mma.sync.aligned.m16n8k16.row.col.f32.f16.f16.f32 "
        "{%0,%1,%2,%3}, {%4,%5,%6,%7}, {%8,%9}, {%0,%1,%2,%3};"
        : "+f"(c[0]), "+f"(c[1]), "+f"(c[2]), "+f"(c[3])
        : "r"(a[0]), "r"(a[1]), "r"(a[2]), "r"(a[3]), "r"(b0), "r"(b1));
}
__device__ __forceinline__ u32 packh2(float lo, float hi) {
    __half2 h = __floats2half2_rn(lo, hi);   // .x = lo
    return *(u32*)&h;
}
__device__ __forceinline__ float ex2(float x) {
    float r;
    asm("ex2.approx.f32 %0, %1;" : "=f"(r) : "f"(x));
    return r;
}
__device__ __forceinline__ void cpa16(u32 dst, const void* src) {
    asm volatile("cp.async.cg.shared.global [%0], [%1], 16;"
                 :: "r"(dst), "l"(src));
}
#define CP_COMMIT() asm volatile("cp.async.commit_group;" ::: "memory")
#define CP_WAIT0()  asm volatile("cp.async.wait_group 0;" ::: "memory")

// q pre-scale: (1/8) * log2(e) so exp(q.k/8) == exp2(q'.k)
#define QSCALE 0.18033688011112042f

// ---------------- scratch (device globals; no allocation allowed) ----------
__device__ __half g_q[(size_t)B_ * N_ * D_];    // pre-scaled by log2e/8
__device__ __half g_k[(size_t)B_ * N_ * D_];
__device__ __half g_v[(size_t)B_ * D_ * N_];    // transposed [B][64][N]

// ============================================================================
// Kernel 1: projections via mma.sync fp16 (champion version).
// ============================================================================
#define PSM_XS 0                      // [128][144] = 18432
#define PSM_WT 18432                  // [64][144]  = 9216
#define PSM_BS 27648                  // 64 floats  = 256
#define PSM_VO 27904                  // [64][272]  = 17408
#define PROJ_SMEM_BYTES 45312

__global__ __launch_bounds__(256) void proj_qkv(
    const float* __restrict__ x,
    const float* __restrict__ Wq, const float* __restrict__ bq,
    const float* __restrict__ Wk, const float* __restrict__ bk,
    const float* __restrict__ Wv, const float* __restrict__ bv)
{
    extern __shared__ char psm[];
    const u32 sp = smem_u32(psm);
    float* bs = (float*)(psm + PSM_BS);

    const int tid = threadIdx.x;
    const int w   = tid >> 5;
    const int t   = tid & 31;
    const int b   = blockIdx.y;
    const int n0  = blockIdx.x * 128;

    // x tile -> fp16 smem (stride 144)
    {
        const float* xb = x + ((size_t)(b * N_) + n0) * D_;
        for (int it = 0; it < 8; ++it) {
            int idx = tid + it * 256;        // 0..2047 float4 units
            int n = idx >> 4, k4 = idx & 15;
            float4 v = *(const float4*)&xb[(size_t)n * D_ + k4 * 4];
            uint2 h;
            h.x = packh2(v.x, v.y);
            h.y = packh2(v.z, v.w);
            *(uint2*)(psm + PSM_XS + n * 144 + k4 * 8) = h;
        }
    }

    const u32 rowSel = (u32)((w * 16 + (t & 15)) * 144 + (t >> 4) * 16);
    const u32 grpSel = (u32)((t & 15) * 144 + (t >> 4) * 16);

    for (int mat = 0; mat < 3; ++mat) {
        const float* W  = (mat == 0) ? Wq : (mat == 1) ? Wk : Wv;
        const float* bb = (mat == 0) ? bq : (mat == 1) ? bk : bv;

        __syncthreads();
        for (int it = 0; it < 2; ++it) {
            int idx = tid + it * 256;        // 0..511
            int k = idx >> 3, d0 = (idx & 7) * 8;
            float4 w0 = *(const float4*)&W[k * 64 + d0];
            float4 w1 = *(const float4*)&W[k * 64 + d0 + 4];
            float wv8[8] = {w0.x, w0.y, w0.z, w0.w, w1.x, w1.y, w1.z, w1.w};
            #pragma unroll
            for (int j = 0; j < 8; ++j)
                *(__half*)(psm + PSM_WT + (d0 + j) * 144 + k * 2) = __float2half(wv8[j]);
        }
        if (tid < 64) bs[tid] = bb[tid];
        __syncthreads();

        if (mat < 2) {
            float acc[4][2][4];
            #pragma unroll
            for (int nt = 0; nt < 4; ++nt)
                #pragma unroll
                for (int j = 0; j < 2; ++j)
                    #pragma unroll
                    for (int e = 0; e < 4; ++e) acc[nt][j][e] = 0.f;

            #pragma unroll
            for (int ks = 0; ks < 4; ++ks) {
                u32 a[4];
                ldm4(a, sp + PSM_XS + rowSel + ks * 32);
                #pragma unroll
                for (int nt = 0; nt < 4; ++nt) {
                    u32 bw[4];
                    ldm4(bw, sp + PSM_WT + (u32)(nt * 2304) + grpSel + ks * 32);
                    mma_f16(acc[nt][0], a, bw[0], bw[2]);
                    mma_f16(acc[nt][1], a, bw[1], bw[3]);
                }
            }

            __half* g = (mat == 0) ? g_q : g_k;
            const float sc = (mat == 0) ? QSCALE : 1.f;
            const size_t r0g = (size_t)(b * N_ + n0 + w * 16 + (t >> 2));
            #pragma unroll
            for (int nt = 0; nt < 4; ++nt) {
                #pragma unroll
                for (int j = 0; j < 2; ++j) {
                    const int c0 = nt * 16 + (t & 3) * 2 + j * 8;
                    const float b0 = bs[c0], b1 = bs[c0 + 1];
                    *(u32*)&g[r0g * 64 + c0] =
                        packh2((acc[nt][j][0] + b0) * sc, (acc[nt][j][1] + b1) * sc);
                    *(u32*)&g[(r0g + 8) * 64 + c0] =
                        packh2((acc[nt][j][2] + b0) * sc, (acc[nt][j][3] + b1) * sc);
                }
            }
        } else {
            float acc[4][2][4];
            #pragma unroll
            for (int mt = 0; mt < 4; ++mt)
                #pragma unroll
                for (int j = 0; j < 2; ++j)
                    #pragma unroll
                    for (int e = 0; e < 4; ++e) acc[mt][j][e] = 0.f;

            #pragma unroll
            for (int ks = 0; ks < 4; ++ks) {
                u32 bx[4];
                ldm4(bx, sp + PSM_XS + rowSel + ks * 32);
                #pragma unroll
                for (int mt = 0; mt < 4; ++mt) {
                    u32 a[4];
                    ldm4(a, sp + PSM_WT + (u32)(mt * 2304) + grpSel + ks * 32);
                    mma_f16(acc[mt][0], a, bx[0], bx[2]);
                    mma_f16(acc[mt][1], a, bx[1], bx[3]);
                }
            }

            #pragma unroll
            for (int mt = 0; mt < 4; ++mt) {
                const int d0 = mt * 16 + (t >> 2);
                const float bv0 = bs[d0], bv1 = bs[d0 + 8];
                #pragma unroll
                for (int j = 0; j < 2; ++j) {
                    const int n = w * 16 + (t & 3) * 2 + j * 8;
                    *(u32*)(psm + PSM_VO + d0 * 272 + n * 2) =
                        packh2(acc[mt][j][0] + bv0, acc[mt][j][1] + bv0);
                    *(u32*)(psm + PSM_VO + (d0 + 8) * 272 + n * 2) =
                        packh2(acc[mt][j][2] + bv1, acc[mt][j][3] + bv1);
                }
            }
            __syncthreads();
            for (int it = 0; it < 4; ++it) {
                int idx = tid + it * 256;        // 0..1023 uint4 units
                int d = idx >> 4, n16 = idx & 15;
                uint4 val = *(uint4*)(psm + PSM_VO + d * 272 + n16 * 16);
                *(uint4*)&g_v[((size_t)(b * 64 + d)) * N_ + n0 + n16 * 8] = val;
            }
        }
    }
}

// ============================================================================
// Kernel 2: masked attention + FUSED output projection. 3 CTAs/SM target.
// grid (16, 16) = (q-tile of 128 rows, batch). 256 threads = 8 warps.
// Multiply masking: h = exp2(s) * (float)adj (adj is exactly 0/1).
// Phase 1: S-MMA -> h -> row-sum -> PV-MMA. No mask caching.
// Epilogue: fused ctx@Wo and concat-proj relu -> y.
// Phase 2: S-MMA recompute, re-read adj, attn = h*adj/L.
// ============================================================================
#define SM_RL    0                    // rowL[128]@0 (512B), bo@512, bl@768
#define SM_BUF   1024                 // two buffers
#define BUF_SZ   36864                // K [128][144]=18432 + V [64][272]=17408
#define ATTN_SMEM (SM_BUF + 2 * BUF_SZ)   // 74752
// epilogue overlay (on top of the double buffers)
#define EP_X     1024                 // x fp16 [128][144] = 18432
#define EP_WO    (EP_X + 18432)       // Wo^T  [64][144] = 9216
#define EP_WLT   (EP_WO + 9216)       // Wl_top^T
#define EP_WLB   (EP_WLT + 9216)      // Wl_bot^T   (end 47104 < 74752)

__global__ void __launch_bounds__(256, 3) attn_kernel(
    const int* __restrict__ adj,
    const float* __restrict__ x,
    const float* __restrict__ Wo, const float* __restrict__ bo,
    const float* __restrict__ Wl, const float* __restrict__ bl,
    float* __restrict__ y, float* __restrict__ attn)
{
    extern __shared__ char smem[];
    const u32 sb = smem_u32(smem);
    float* rowL = (float*)(smem + SM_RL);
    float* bof  = (float*)(smem + 512);
    float* blf  = (float*)(smem + 768);

    const int tid = threadIdx.x;
    const int w   = tid >> 5;
    const int t   = tid & 31;
    const int b   = blockIdx.y;
    const int r0  = blockIdx.x * 128;

    const int rowA = t >> 2;            // 0..7
    const int colq = (t & 3) * 2;       // 0,2,4,6
    const u32 aSel  = (u32)((w * 16 + (t & 15)) * 144 + (t >> 4) * 16);
    const u32 bSel  = (u32)((t & 15) * 144 + (t >> 4) * 16);
    const u32 bSel2 = (u32)((t & 15) * 272 + (t >> 4) * 16);

    // ---- stage Q in buf0 K-slot, extract A-fragments ----
    {
        const size_t qbase = ((size_t)b * N_ + r0) * D_;
        for (int it = 0; it < 4; ++it) {
            int idx = tid + it * 256;
            int r = idx >> 3, c = idx & 7;
            *(uint4*)(smem + SM_BUF + r * 144 + c * 16) =
                *(const uint4*)&g_q[qbase + (size_t)r * D_ + c * 8];
        }
    }
    __syncthreads();
    u32 qa[4][4];
    #pragma unroll
    for (int ks = 0; ks < 4; ++ks) ldm4(qa[ks], sb + SM_BUF + aSel + ks * 32);
    __syncthreads();   // everyone extracted Q before buf0 is overwritten

    float sumA = 0.f, sumB = 0.f;
    float acc2[8][4];
    #pragma unroll
    for (int g = 0; g < 8; ++g)
        #pragma unroll
        for (int j = 0; j < 4; ++j) acc2[g][j] = 0.f;

    const size_t growA = (size_t)(b * N_ + r0 + w * 16 + rowA) * N_;
    const size_t growB = growA + (size_t)8 * N_;
    const size_t kgbase = (size_t)b * N_ * D_;
    const size_t vgbase = (size_t)b * D_ * N_;

    // prologue: async-load tile 0 (K + V)
    {
        for (int it = 0; it < 4; ++it) {
            int idx = tid + it * 256;
            int r = idx >> 3, c = idx & 7;
            cpa16(sb + SM_BUF + r * 144 + c * 16,
                  &g_k[kgbase + (size_t)r * D_ + c * 8]);
            int d = idx >> 4, c8 = idx & 15;
            cpa16(sb + SM_BUF + 18432 + d * 272 + c8 * 16,
                  &g_v[vgbase + (size_t)d * N_ + c8 * 8]);
        }
        CP_COMMIT();
    }

    // =================== Phase 1: S -> h -> sums + PV ===================
    for (int mt = 0; mt < 16; ++mt) {
        CP_WAIT0();
        __syncthreads();
        if (mt < 15) {
            const int m1 = (mt + 1) * 128;
            const u32 nb = sb + SM_BUF + ((mt + 1) & 1) * BUF_SZ;
            for (int it = 0; it < 4; ++it) {
                int idx = tid + it * 256;
                int r = idx >> 3, c = idx & 7;
                cpa16(nb + r * 144 + c * 16,
                      &g_k[kgbase + (size_t)(m1 + r) * D_ + c * 8]);
                int d = idx >> 4, c8 = idx & 15;
                cpa16(nb + 18432 + d * 272 + c8 * 16,
                      &g_v[vgbase + (size_t)d * N_ + m1 + c8 * 8]);
            }
            CP_COMMIT();
        }

        const u32 sbK = sb + SM_BUF + (mt & 1) * BUF_SZ;
        const u32 sbV = sbK + 18432;
        const int m0 = mt * 128;

        #pragma unroll
        for (int kk = 0; kk < 8; ++kk) {
            float acc[2][4];
            #pragma unroll
            for (int j = 0; j < 4; ++j) { acc[0][j] = 0.f; acc[1][j] = 0.f; }
            #pragma unroll
            for (int ks = 0; ks < 4; ++ks) {
                u32 bh[4];
                ldm4(bh, sbK + (u32)(kk * 2304) + bSel + ks * 32);
                mma_f16(acc[0], qa[ks], bh[0], bh[2]);
                mma_f16(acc[1], qa[ks], bh[1], bh[3]);
            }
            const int C0 = kk * 16 + colq;
            int2 a0A = *(const int2*)&adj[growA + m0 + C0];
            int2 a1A = *(const int2*)&adj[growA + m0 + C0 + 8];
            int2 a0B = *(const int2*)&adj[growB + m0 + C0];
            int2 a1B = *(const int2*)&adj[growB + m0 + C0 + 8];
            // multiply masking: adj is exactly 0 or 1
            float h00 = ex2(acc[0][0]) * (float)a0A.x;
            float h01 = ex2(acc[0][1]) * (float)a0A.y;
            float h02 = ex2(acc[0][2]) * (float)a0B.x;
            float h03 = ex2(acc[0][3]) * (float)a0B.y;
            float h10 = ex2(acc[1][0]) * (float)a1A.x;
            float h11 = ex2(acc[1][1]) * (float)a1A.y;
            float h12 = ex2(acc[1][2]) * (float)a1B.x;
            float h13 = ex2(acc[1][3]) * (float)a1B.y;
            sumA += h00 + h01 + h10 + h11;
            sumB += h02 + h03 + h12 + h13;

            u32 af[4];
            af[0] = packh2(h00, h01);
            af[1] = packh2(h02, h03);
            af[2] = packh2(h10, h11);
            af[3] = packh2(h12, h13);
            #pragma unroll
            for (int gd = 0; gd < 4; ++gd) {
                u32 bh[4];
                ldm4(bh, sbV + (u32)(gd * 4352) + bSel2 + kk * 32);
                mma_f16(acc2[2 * gd],     af, bh[0], bh[2]);
                mma_f16(acc2[2 * gd + 1], af, bh[1], bh[3]);
            }
        }
    }

    // row sums -> 1/L (quad reduce; no max needed: scores bounded)
    sumA += __shfl_xor_sync(0xffffffffu, sumA, 1);
    sumA += __shfl_xor_sync(0xffffffffu, sumA, 2);
    sumB += __shfl_xor_sync(0xffffffffu, sumB, 1);
    sumB += __shfl_xor_sync(0xffffffffu, sumB, 2);
    __syncthreads();   // phase-1 MMAs done reading buffers
    if ((t & 3) == 0) {
        rowL[w * 16 + rowA]     = 1.f / sumA;
        rowL[w * 16 + rowA + 8] = 1.f / sumB;
    }
    if (tid < 64) { bof[tid] = bo[tid]; blf[tid] = bl[tid]; }
    __syncthreads();
    const float iL0 = rowL[w * 16 + rowA];
    const float iL1 = rowL[w * 16 + rowA + 8];

    // ============ FUSED out_proj epilogue ============
    {
        const float* xb = x + ((size_t)(b * N_) + r0) * D_;
        for (int it = 0; it < 8; ++it) {
            int idx = tid + it * 256;
            int n = idx >> 4, k4 = idx & 15;
            float4 v = *(const float4*)&xb[(size_t)n * D_ + k4 * 4];
            uint2 hh;
            hh.x = packh2(v.x, v.y);
            hh.y = packh2(v.z, v.w);
            *(uint2*)(smem + EP_X + n * 144 + k4 * 8) = hh;
        }
        for (int it = 0; it < 2; ++it) {
            int idx = tid + it * 256;
            int k = idx >> 3, d0 = (idx & 7) * 8;
            #pragma unroll
            for (int m = 0; m < 3; ++m) {
                const float* W = (m == 0) ? &Wo[k * 64 + d0]
                              : (m == 1) ? &Wl[k * 64 + d0]
                                         : &Wl[(64 + k) * 64 + d0];
                const u32 base = (m == 0) ? EP_WO : (m == 1) ? EP_WLT : EP_WLB;
                float4 w0 = *(const float4*)W;
                float4 w1 = *(const float4*)(W + 4);
                float wv8[8] = {w0.x, w0.y, w0.z, w0.w, w1.x, w1.y, w1.z, w1.w};
                #pragma unroll
                for (int j = 0; j < 8; ++j)
                    *(__half*)(smem + base + (d0 + j) * 144 + k * 2) = __float2half(wv8[j]);
            }
        }
    }
    __syncthreads();

    {
        u32 cfA[4][4];
        #pragma unroll
        for (int ks = 0; ks < 4; ++ks) {
            cfA[ks][0] = packh2(acc2[2 * ks][0] * iL0,     acc2[2 * ks][1] * iL0);
            cfA[ks][1] = packh2(acc2[2 * ks][2] * iL1,     acc2[2 * ks][3] * iL1);
            cfA[ks][2] = packh2(acc2[2 * ks + 1][0] * iL0, acc2[2 * ks + 1][1] * iL0);
            cfA[ks][3] = packh2(acc2[2 * ks + 1][2] * iL1, acc2[2 * ks + 1][3] * iL1);
        }
        float co[8][4];
        #pragma unroll
        for (int g = 0; g < 8; ++g)
            #pragma unroll
            for (int j = 0; j < 4; ++j) co[g][j] = 0.f;
        #pragma unroll
        for (int ks = 0; ks < 4; ++ks) {
            #pragma unroll
            for (int g = 0; g < 4; ++g) {
                u32 bw[4];
                ldm4(bw, sb + EP_WO + (u32)(g * 2304) + bSel + ks * 32);
                mma_f16(co[2 * g],     cfA[ks], bw[0], bw[2]);
                mma_f16(co[2 * g + 1], cfA[ks], bw[1], bw[3]);
            }
        }

        u32 cf2[4][4];
        #pragma unroll
        for (int ks = 0; ks < 4; ++ks) {
            const int c0 = ks * 16 + colq;
            cf2[ks][0] = packh2(co[2 * ks][0] + bof[c0],     co[2 * ks][1] + bof[c0 + 1]);
            cf2[ks][1] = packh2(co[2 * ks][2] + bof[c0],     co[2 * ks][3] + bof[c0 + 1]);
            cf2[ks][2] = packh2(co[2 * ks + 1][0] + bof[c0 + 8], co[2 * ks + 1][1] + bof[c0 + 9]);
            cf2[ks][3] = packh2(co[2 * ks + 1][2] + bof[c0 + 8], co[2 * ks + 1][3] + bof[c0 + 9]);
        }

        float ya[8][4];
        #pragma unroll
        for (int g = 0; g < 8; ++g)
            #pragma unroll
            for (int j = 0; j < 4; ++j) ya[g][j] = 0.f;
        #pragma unroll
        for (int ks = 0; ks < 4; ++ks) {
            u32 ax[4];
            ldm4(ax, sb + EP_X + aSel + ks * 32);
            #pragma unroll
            for (int g = 0; g < 4; ++g) {
                u32 bw[4];
                ldm4(bw, sb + EP_WLT + (u32)(g * 2304) + bSel + ks * 32);
                mma_f16(ya[2 * g],     ax, bw[0], bw[2]);
                mma_f16(ya[2 * g + 1], ax, bw[1], bw[3]);
            }
        }
        #pragma unroll
        for (int ks = 0; ks < 4; ++ks) {
            #pragma unroll
            for (int g = 0; g < 4; ++g) {
                u32 bw[4];
                ldm4(bw, sb + EP_WLB + (u32)(g * 2304) + bSel + ks * 32);
                mma_f16(ya[2 * g],     cf2[ks], bw[0], bw[2]);
                mma_f16(ya[2 * g + 1], cf2[ks], bw[1], bw[3]);
            }
        }

        const size_t yrA = (size_t)(b * N_ + r0 + w * 16 + rowA) * D_;
        const size_t yrB = yrA + (size_t)8 * D_;
        #pragma unroll
        for (int g = 0; g < 8; ++g) {
            const int C = g * 8 + colq;
            const float b0 = blf[C], b1 = blf[C + 1];
            *(float2*)&y[yrA + C] = make_float2(fmaxf(ya[g][0] + b0, 0.f),
                                                fmaxf(ya[g][1] + b1, 0.f));
            *(float2*)&y[yrB + C] = make_float2(fmaxf(ya[g][2] + b0, 0.f),
                                                fmaxf(ya[g][3] + b1, 0.f));
        }
    }
    __syncthreads();   // epilogue smem reads done before buffers reused

    // prologue: async-load K tile 0 for phase 2
    {
        for (int it = 0; it < 4; ++it) {
            int idx = tid + it * 256;
            int r = idx >> 3, c = idx & 7;
            cpa16(sb + SM_BUF + r * 144 + c * 16,
                  &g_k[kgbase + (size_t)r * D_ + c * 8]);
        }
        CP_COMMIT();
    }

    // =================== Phase 2: S recompute -> attn = h*adj/L =============
    for (int mt = 0; mt < 16; ++mt) {
        CP_WAIT0();
        __syncthreads();
        if (mt < 15) {
            const int m1 = (mt + 1) * 128;
            const u32 nb = sb + SM_BUF + ((mt + 1) & 1) * BUF_SZ;
            for (int it = 0; it < 4; ++it) {
                int idx = tid + it * 256;
                int r = idx >> 3, c = idx & 7;
                cpa16(nb + r * 144 + c * 16,
                      &g_k[kgbase + (size_t)(m1 + r) * D_ + c * 8]);
            }
            CP_COMMIT();
        }

        const u32 sbK = sb + SM_BUF + (mt & 1) * BUF_SZ;
        const int m0 = mt * 128;

        #pragma unroll
        for (int kk = 0; kk < 8; ++kk) {
            const int C0 = kk * 16 + colq;
            int2 a0A = *(const int2*)&adj[growA + m0 + C0];
            int2 a1A = *(const int2*)&adj[growA + m0 + C0 + 8];
            int2 a0B = *(const int2*)&adj[growB + m0 + C0];
            int2 a1B = *(const int2*)&adj[growB + m0 + C0 + 8];

            float acc[2][4];
            #pragma unroll
            for (int j = 0; j < 4; ++j) { acc[0][j] = 0.f; acc[1][j] = 0.f; }
            #pragma unroll
            for (int ks = 0; ks < 4; ++ks) {
                u32 bh[4];
                ldm4(bh, sbK + (u32)(kk * 2304) + bSel + ks * 32);
                mma_f16(acc[0], qa[ks], bh[0], bh[2]);
                mma_f16(acc[1], qa[ks], bh[1], bh[3]);
            }

            float p00 = ex2(acc[0][0]) * (float)a0A.x * iL0;
            float p01 = ex2(acc[0][1]) * (float)a0A.y * iL0;
            float p02 = ex2(acc[0][2]) * (float)a0B.x * iL1;
            float p03 = ex2(acc[0][3]) * (float)a0B.y * iL1;
            float p10 = ex2(acc[1][0]) * (float)a1A.x * iL0;
            float p11 = ex2(acc[1][1]) * (float)a1A.y * iL0;
            float p12 = ex2(acc[1][2]) * (float)a1B.x * iL1;
            float p13 = ex2(acc[1][3]) * (float)a1B.y * iL1;
            *(float2*)&attn[growA + m0 + C0]     = make_float2(p00, p01);
            *(float2*)&attn[growA + m0 + C0 + 8] = make_float2(p10, p11);
            *(float2*)&attn[growB + m0 + C0]     = make_float2(p02, p03);
            *(float2*)&attn[growB + m0 + C0 + 8] = make_float2(p12, p13);
        }
    }
}

// ============================================================================
extern "C" void kernel_launch(void* const* d_in, const int* in_sizes, int n_in,
                              void* d_out, int out_size)
{
    const float* x   = (const float*)d_in[0];
    const int*   adj = (const int*)  d_in[1];
    const float* Wq  = (const float*)d_in[2];
    const float* bq  = (const float*)d_in[3];
    const float* Wk  = (const float*)d_in[4];
    const float* bk  = (const float*)d_in[5];
    const float* Wv  = (const float*)d_in[6];
    const float* bv  = (const float*)d_in[7];
    const float* Wo  = (const float*)d_in[8];
    const float* bo  = (const float*)d_in[9];
    const float* Wl  = (const float*)d_in[10];
    const float* bl  = (const float*)d_in[11];

    float* y    = (float*)d_out;                         // [B,N,D]
    float* attn = (float*)d_out + (size_t)B_ * N_ * D_;  // [B,N,N]

    cudaFuncSetAttribute(proj_qkv,
                         cudaFuncAttributeMaxDynamicSharedMemorySize,
                         PROJ_SMEM_BYTES);
    cudaFuncSetAttribute(attn_kernel,
                         cudaFuncAttributeMaxDynamicSharedMemorySize,
                         ATTN_SMEM);

    proj_qkv<<<dim3(16, 16), 256, PROJ_SMEM_BYTES>>>(x, Wq, bq, Wk, bk, Wv, bv);
    attn_kernel<<<dim3(16, 16), 256, ATTN_SMEM>>>(adj, x, Wo, bo, Wl, bl, y, attn);
}

// round 17
// speedup vs baseline: 1.2909x; 1.2909x over previous
#include <cuda_runtime.h>
#include <cuda_fp16.h>
#include <math.h>
#include <stdint.h>

#define B_ 16
#define N_ 2048
#define D_ 64

typedef unsigned int u32;

// ---------------------------- helpers ---------------------------------------
__device__ __forceinline__ u32 smem_u32(const void* p) {
    u32 a;
    asm("{ .reg .u64 t; cvta.to.shared.u64 t, %1; cvt.u32.u64 %0, t; }"
        : "=r"(a) : "l"(p));
    return a;
}
__device__ __forceinline__ void ldm4(u32* r, u32 a) {
    asm volatile("ldmatrix.sync.aligned.m8n8.x4.shared.b16 {%0,%1,%2,%3}, [%4];"
        : "=r"(r[0]), "=r"(r[1]), "=r"(r[2]), "=r"(r[3]) : "r"(a));
}
__device__ __forceinline__ void mma_f16(float* c, const u32* a, u32 b0, u32 b1) {
    asm volatile("mma.sync.aligned.m16n8k16.row.col.f32.f16.f16.f32 "
        "{%0,%1,%2,%3}, {%4,%5,%6,%7}, {%8,%9}, {%0,%1,%2,%3};"
        : "+f"(c[0]), "+f"(c[1]), "+f"(c[2]), "+f"(c[3])
        : "r"(a[0]), "r"(a[1]), "r"(a[2]), "r"(a[3]), "r"(b0), "r"(b1));
}
__device__ __forceinline__ u32 packh2(float lo, float hi) {
    __half2 h = __floats2half2_rn(lo, hi);   // .x = lo
    return *(u32*)&h;
}
__device__ __forceinline__ float ex2(float x) {
    float r;
    asm("ex2.approx.f32 %0, %1;" : "=f"(r) : "f"(x));
    return r;
}
__device__ __forceinline__ void cpa16(u32 dst, const void* src) {
    asm volatile("cp.async.cg.shared.global [%0], [%1], 16;"
                 :: "r"(dst), "l"(src));
}
#define CP_COMMIT() asm volatile("cp.async.commit_group;" ::: "memory")
#define CP_WAIT0()  asm volatile("cp.async.wait_group 0;" ::: "memory")

// q pre-scale: (1/8) * log2(e) so exp(q.k/8) == exp2(q'.k)
#define QSCALE 0.18033688011112042f

// ---------------- scratch (device globals; no allocation allowed) ----------
__device__ __half g_q[(size_t)B_ * N_ * D_];    // pre-scaled by log2e/8
__device__ __half g_k[(size_t)B_ * N_ * D_];
__device__ __half g_v[(size_t)B_ * D_ * N_];    // transposed [B][64][N]

// ============================================================================
// Kernel 1: projections via mma.sync fp16 (champion version).
// ============================================================================
#define PSM_XS 0                      // [128][144] = 18432
#define PSM_WT 18432                  // [64][144]  = 9216
#define PSM_BS 27648                  // 64 floats  = 256
#define PSM_VO 27904                  // [64][272]  = 17408
#define PROJ_SMEM_BYTES 45312

__global__ __launch_bounds__(256) void proj_qkv(
    const float* __restrict__ x,
    const float* __restrict__ Wq, const float* __restrict__ bq,
    const float* __restrict__ Wk, const float* __restrict__ bk,
    const float* __restrict__ Wv, const float* __restrict__ bv)
{
    extern __shared__ char psm[];
    const u32 sp = smem_u32(psm);
    float* bs = (float*)(psm + PSM_BS);

    const int tid = threadIdx.x;
    const int w   = tid >> 5;
    const int t   = tid & 31;
    const int b   = blockIdx.y;
    const int n0  = blockIdx.x * 128;

    // x tile -> fp16 smem (stride 144)
    {
        const float* xb = x + ((size_t)(b * N_) + n0) * D_;
        for (int it = 0; it < 8; ++it) {
            int idx = tid + it * 256;        // 0..2047 float4 units
            int n = idx >> 4, k4 = idx & 15;
            float4 v = *(const float4*)&xb[(size_t)n * D_ + k4 * 4];
            uint2 h;
            h.x = packh2(v.x, v.y);
            h.y = packh2(v.z, v.w);
            *(uint2*)(psm + PSM_XS + n * 144 + k4 * 8) = h;
        }
    }

    const u32 rowSel = (u32)((w * 16 + (t & 15)) * 144 + (t >> 4) * 16);
    const u32 grpSel = (u32)((t & 15) * 144 + (t >> 4) * 16);

    for (int mat = 0; mat < 3; ++mat) {
        const float* W  = (mat == 0) ? Wq : (mat == 1) ? Wk : Wv;
        const float* bb = (mat == 0) ? bq : (mat == 1) ? bk : bv;

        __syncthreads();
        for (int it = 0; it < 2; ++it) {
            int idx = tid + it * 256;        // 0..511
            int k = idx >> 3, d0 = (idx & 7) * 8;
            float4 w0 = *(const float4*)&W[k * 64 + d0];
            float4 w1 = *(const float4*)&W[k * 64 + d0 + 4];
            float wv8[8] = {w0.x, w0.y, w0.z, w0.w, w1.x, w1.y, w1.z, w1.w};
            #pragma unroll
            for (int j = 0; j < 8; ++j)
                *(__half*)(psm + PSM_WT + (d0 + j) * 144 + k * 2) = __float2half(wv8[j]);
        }
        if (tid < 64) bs[tid] = bb[tid];
        __syncthreads();

        if (mat < 2) {
            float acc[4][2][4];
            #pragma unroll
            for (int nt = 0; nt < 4; ++nt)
                #pragma unroll
                for (int j = 0; j < 2; ++j)
                    #pragma unroll
                    for (int e = 0; e < 4; ++e) acc[nt][j][e] = 0.f;

            #pragma unroll
            for (int ks = 0; ks < 4; ++ks) {
                u32 a[4];
                ldm4(a, sp + PSM_XS + rowSel + ks * 32);
                #pragma unroll
                for (int nt = 0; nt < 4; ++nt) {
                    u32 bw[4];
                    ldm4(bw, sp + PSM_WT + (u32)(nt * 2304) + grpSel + ks * 32);
                    mma_f16(acc[nt][0], a, bw[0], bw[2]);
                    mma_f16(acc[nt][1], a, bw[1], bw[3]);
                }
            }

            __half* g = (mat == 0) ? g_q : g_k;
            const float sc = (mat == 0) ? QSCALE : 1.f;
            const size_t r0g = (size_t)(b * N_ + n0 + w * 16 + (t >> 2));
            #pragma unroll
            for (int nt = 0; nt < 4; ++nt) {
                #pragma unroll
                for (int j = 0; j < 2; ++j) {
                    const int c0 = nt * 16 + (t & 3) * 2 + j * 8;
                    const float b0 = bs[c0], b1 = bs[c0 + 1];
                    *(u32*)&g[r0g * 64 + c0] =
                        packh2((acc[nt][j][0] + b0) * sc, (acc[nt][j][1] + b1) * sc);
                    *(u32*)&g[(r0g + 8) * 64 + c0] =
                        packh2((acc[nt][j][2] + b0) * sc, (acc[nt][j][3] + b1) * sc);
                }
            }
        } else {
            float acc[4][2][4];
            #pragma unroll
            for (int mt = 0; mt < 4; ++mt)
                #pragma unroll
                for (int j = 0; j < 2; ++j)
                    #pragma unroll
                    for (int e = 0; e < 4; ++e) acc[mt][j][e] = 0.f;

            #pragma unroll
            for (int ks = 0; ks < 4; ++ks) {
                u32 bx[4];
                ldm4(bx, sp + PSM_XS + rowSel + ks * 32);
                #pragma unroll
                for (int mt = 0; mt < 4; ++mt) {
                    u32 a[4];
                    ldm4(a, sp + PSM_WT + (u32)(mt * 2304) + grpSel + ks * 32);
                    mma_f16(acc[mt][0], a, bx[0], bx[2]);
                    mma_f16(acc[mt][1], a, bx[1], bx[3]);
                }
            }

            #pragma unroll
            for (int mt = 0; mt < 4; ++mt) {
                const int d0 = mt * 16 + (t >> 2);
                const float bv0 = bs[d0], bv1 = bs[d0 + 8];
                #pragma unroll
                for (int j = 0; j < 2; ++j) {
                    const int n = w * 16 + (t & 3) * 2 + j * 8;
                    *(u32*)(psm + PSM_VO + d0 * 272 + n * 2) =
                        packh2(acc[mt][j][0] + bv0, acc[mt][j][1] + bv0);
                    *(u32*)(psm + PSM_VO + (d0 + 8) * 272 + n * 2) =
                        packh2(acc[mt][j][2] + bv1, acc[mt][j][3] + bv1);
                }
            }
            __syncthreads();
            for (int it = 0; it < 4; ++it) {
                int idx = tid + it * 256;        // 0..1023 uint4 units
                int d = idx >> 4, n16 = idx & 15;
                uint4 val = *(uint4*)(psm + PSM_VO + d * 272 + n16 * 16);
                *(uint4*)&g_v[((size_t)(b * 64 + d)) * N_ + n0 + n16 * 8] = val;
            }
        }
    }
}

// ============================================================================
// Kernel 2: masked attention + FUSED output projection (R15 champion + ALU trim).
// grid (16, 16) = (q-tile of 128 rows, batch). 256 threads = 8 warps.
// Phase 1: S-MMA -> h = exp2(s)*adj (multiply masking; adj is exactly 0/1)
//          -> row-sum -> PV-MMA. Mask bits packed via OR/shift (no compares).
// Epilogue: fused ctx@Wo and concat-proj relu -> y.
// Phase 2: S-MMA recompute -> select on cached bits -> attn = h/L.
// ============================================================================
#define SM_RL    0                    // rowL[128]@0 (512B), bo@512, bl@768
#define SM_MASK  1024                 // 16 tiles * 256 threads * 8 B = 32768
#define SM_BUF   33792                // two buffers
#define BUF_SZ   36864                // K [128][144]=18432 + V [64][272]=17408
#define ATTN_SMEM (SM_BUF + 2 * BUF_SZ)   // 107520
// epilogue overlay (on top of the double buffers)
#define EP_X     33792                // x fp16 [128][144] = 18432
#define EP_WO    (EP_X + 18432)       // Wo^T  [64][144] = 9216
#define EP_WLT   (EP_WO + 9216)       // Wl_top^T
#define EP_WLB   (EP_WLT + 9216)      // Wl_bot^T   (end 79872 < 107520)

__global__ void __launch_bounds__(256, 2) attn_kernel(
    const int* __restrict__ adj,
    const float* __restrict__ x,
    const float* __restrict__ Wo, const float* __restrict__ bo,
    const float* __restrict__ Wl, const float* __restrict__ bl,
    float* __restrict__ y, float* __restrict__ attn)
{
    extern __shared__ char smem[];
    const u32 sb = smem_u32(smem);
    float* rowL = (float*)(smem + SM_RL);
    float* bof  = (float*)(smem + 512);
    float* blf  = (float*)(smem + 768);
    uint2* maskS = (uint2*)(smem + SM_MASK);

    const int tid = threadIdx.x;
    const int w   = tid >> 5;
    const int t   = tid & 31;
    const int b   = blockIdx.y;
    const int r0  = blockIdx.x * 128;

    const int rowA = t >> 2;            // 0..7
    const int colq = (t & 3) * 2;       // 0,2,4,6
    const u32 aSel  = (u32)((w * 16 + (t & 15)) * 144 + (t >> 4) * 16);
    const u32 bSel  = (u32)((t & 15) * 144 + (t >> 4) * 16);
    const u32 bSel2 = (u32)((t & 15) * 272 + (t >> 4) * 16);

    // ---- stage Q in buf0 K-slot, extract A-fragments ----
    {
        const size_t qbase = ((size_t)b * N_ + r0) * D_;
        for (int it = 0; it < 4; ++it) {
            int idx = tid + it * 256;
            int r = idx >> 3, c = idx & 7;
            *(uint4*)(smem + SM_BUF + r * 144 + c * 16) =
                *(const uint4*)&g_q[qbase + (size_t)r * D_ + c * 8];
        }
    }
    __syncthreads();
    u32 qa[4][4];
    #pragma unroll
    for (int ks = 0; ks < 4; ++ks) ldm4(qa[ks], sb + SM_BUF + aSel + ks * 32);
    __syncthreads();   // everyone extracted Q before buf0 is overwritten

    float sumA = 0.f, sumB = 0.f;
    float acc2[8][4];
    #pragma unroll
    for (int g = 0; g < 8; ++g)
        #pragma unroll
        for (int j = 0; j < 4; ++j) acc2[g][j] = 0.f;

    const size_t growA = (size_t)(b * N_ + r0 + w * 16 + rowA) * N_;
    const size_t growB = growA + (size_t)8 * N_;
    const size_t kgbase = (size_t)b * N_ * D_;
    const size_t vgbase = (size_t)b * D_ * N_;

    // prologue: async-load tile 0 (K + V)
    {
        for (int it = 0; it < 4; ++it) {
            int idx = tid + it * 256;
            int r = idx >> 3, c = idx & 7;
            cpa16(sb + SM_BUF + r * 144 + c * 16,
                  &g_k[kgbase + (size_t)r * D_ + c * 8]);
            int d = idx >> 4, c8 = idx & 15;
            cpa16(sb + SM_BUF + 18432 + d * 272 + c8 * 16,
                  &g_v[vgbase + (size_t)d * N_ + c8 * 8]);
        }
        CP_COMMIT();
    }

    // =================== Phase 1: S -> h -> sums + PV ===================
    for (int mt = 0; mt < 16; ++mt) {
        CP_WAIT0();
        __syncthreads();
        if (mt < 15) {
            const int m1 = (mt + 1) * 128;
            const u32 nb = sb + SM_BUF + ((mt + 1) & 1) * BUF_SZ;
            for (int it = 0; it < 4; ++it) {
                int idx = tid + it * 256;
                int r = idx >> 3, c = idx & 7;
                cpa16(nb + r * 144 + c * 16,
                      &g_k[kgbase + (size_t)(m1 + r) * D_ + c * 8]);
                int d = idx >> 4, c8 = idx & 15;
                cpa16(nb + 18432 + d * 272 + c8 * 16,
                      &g_v[vgbase + (size_t)d * N_ + m1 + c8 * 8]);
            }
            CP_COMMIT();
        }

        const u32 sbK = sb + SM_BUF + (mt & 1) * BUF_SZ;
        const u32 sbV = sbK + 18432;
        const int m0 = mt * 128;
        u32 mlo = 0, mhi = 0;

        #pragma unroll
        for (int kk = 0; kk < 8; ++kk) {
            float acc[2][4];
            #pragma unroll
            for (int j = 0; j < 4; ++j) { acc[0][j] = 0.f; acc[1][j] = 0.f; }
            #pragma unroll
            for (int ks = 0; ks < 4; ++ks) {
                u32 bh[4];
                ldm4(bh, sbK + (u32)(kk * 2304) + bSel + ks * 32);
                mma_f16(acc[0], qa[ks], bh[0], bh[2]);
                mma_f16(acc[1], qa[ks], bh[1], bh[3]);
            }
            const int C0 = kk * 16 + colq;
            int2 a0A = *(const int2*)&adj[growA + m0 + C0];
            int2 a1A = *(const int2*)&adj[growA + m0 + C0 + 8];
            int2 a0B = *(const int2*)&adj[growB + m0 + C0];
            int2 a1B = *(const int2*)&adj[growB + m0 + C0 + 8];
            // multiply masking (adj is exactly 0/1) — no compares
            float h00 = ex2(acc[0][0]) * (float)a0A.x;
            float h01 = ex2(acc[0][1]) * (float)a0A.y;
            float h02 = ex2(acc[0][2]) * (float)a0B.x;
            float h03 = ex2(acc[0][3]) * (float)a0B.y;
            float h10 = ex2(acc[1][0]) * (float)a1A.x;
            float h11 = ex2(acc[1][1]) * (float)a1A.y;
            float h12 = ex2(acc[1][2]) * (float)a1B.x;
            float h13 = ex2(acc[1][3]) * (float)a1B.y;
            // mask bits via OR/shift of 0/1 values — no compares
            u32 byte = (u32)a0A.x | ((u32)a0A.y << 1)
                     | ((u32)a0B.x << 2) | ((u32)a0B.y << 3)
                     | ((u32)a1A.x << 4) | ((u32)a1A.y << 5)
                     | ((u32)a1B.x << 6) | ((u32)a1B.y << 7);
            if (kk < 4) mlo |= byte << (kk * 8); else mhi |= byte << ((kk - 4) * 8);
            sumA += h00 + h01 + h10 + h11;
            sumB += h02 + h03 + h12 + h13;

            u32 af[4];
            af[0] = packh2(h00, h01);
            af[1] = packh2(h02, h03);
            af[2] = packh2(h10, h11);
            af[3] = packh2(h12, h13);
            #pragma unroll
            for (int gd = 0; gd < 4; ++gd) {
                u32 bh[4];
                ldm4(bh, sbV + (u32)(gd * 4352) + bSel2 + kk * 32);
                mma_f16(acc2[2 * gd],     af, bh[0], bh[2]);
                mma_f16(acc2[2 * gd + 1], af, bh[1], bh[3]);
            }
        }
        maskS[mt * 256 + tid] = make_uint2(mlo, mhi);
    }

    // row sums -> 1/L (quad reduce; no max needed: scores bounded)
    sumA += __shfl_xor_sync(0xffffffffu, sumA, 1);
    sumA += __shfl_xor_sync(0xffffffffu, sumA, 2);
    sumB += __shfl_xor_sync(0xffffffffu, sumB, 1);
    sumB += __shfl_xor_sync(0xffffffffu, sumB, 2);
    __syncthreads();   // phase-1 MMAs done reading buffers
    if ((t & 3) == 0) {
        rowL[w * 16 + rowA]     = 1.f / sumA;
        rowL[w * 16 + rowA + 8] = 1.f / sumB;
    }
    if (tid < 64) { bof[tid] = bo[tid]; blf[tid] = bl[tid]; }
    __syncthreads();
    const float iL0 = rowL[w * 16 + rowA];
    const float iL1 = rowL[w * 16 + rowA + 8];

    // ============ FUSED out_proj epilogue ============
    {
        const float* xb = x + ((size_t)(b * N_) + r0) * D_;
        for (int it = 0; it < 8; ++it) {
            int idx = tid + it * 256;
            int n = idx >> 4, k4 = idx & 15;
            float4 v = *(const float4*)&xb[(size_t)n * D_ + k4 * 4];
            uint2 hh;
            hh.x = packh2(v.x, v.y);
            hh.y = packh2(v.z, v.w);
            *(uint2*)(smem + EP_X + n * 144 + k4 * 8) = hh;
        }
        for (int it = 0; it < 2; ++it) {
            int idx = tid + it * 256;
            int k = idx >> 3, d0 = (idx & 7) * 8;
            #pragma unroll
            for (int m = 0; m < 3; ++m) {
                const float* W = (m == 0) ? &Wo[k * 64 + d0]
                              : (m == 1) ? &Wl[k * 64 + d0]
                                         : &Wl[(64 + k) * 64 + d0];
                const u32 base = (m == 0) ? EP_WO : (m == 1) ? EP_WLT : EP_WLB;
                float4 w0 = *(const float4*)W;
                float4 w1 = *(const float4*)(W + 4);
                float wv8[8] = {w0.x, w0.y, w0.z, w0.w, w1.x, w1.y, w1.z, w1.w};
                #pragma unroll
                for (int j = 0; j < 8; ++j)
                    *(__half*)(smem + base + (d0 + j) * 144 + k * 2) = __float2half(wv8[j]);
            }
        }
    }
    __syncthreads();

    {
        u32 cfA[4][4];
        #pragma unroll
        for (int ks = 0; ks < 4; ++ks) {
            cfA[ks][0] = packh2(acc2[2 * ks][0] * iL0,     acc2[2 * ks][1] * iL0);
            cfA[ks][1] = packh2(acc2[2 * ks][2] * iL1,     acc2[2 * ks][3] * iL1);
            cfA[ks][2] = packh2(acc2[2 * ks + 1][0] * iL0, acc2[2 * ks + 1][1] * iL0);
            cfA[ks][3] = packh2(acc2[2 * ks + 1][2] * iL1, acc2[2 * ks + 1][3] * iL1);
        }
        float co[8][4];
        #pragma unroll
        for (int g = 0; g < 8; ++g)
            #pragma unroll
            for (int j = 0; j < 4; ++j) co[g][j] = 0.f;
        #pragma unroll
        for (int ks = 0; ks < 4; ++ks) {
            #pragma unroll
            for (int g = 0; g < 4; ++g) {
                u32 bw[4];
                ldm4(bw, sb + EP_WO + (u32)(g * 2304) + bSel + ks * 32);
                mma_f16(co[2 * g],     cfA[ks], bw[0], bw[2]);
                mma_f16(co[2 * g + 1], cfA[ks], bw[1], bw[3]);
            }
        }

        u32 cf2[4][4];
        #pragma unroll
        for (int ks = 0; ks < 4; ++ks) {
            const int c0 = ks * 16 + colq;
            cf2[ks][0] = packh2(co[2 * ks][0] + bof[c0],     co[2 * ks][1] + bof[c0 + 1]);
            cf2[ks][1] = packh2(co[2 * ks][2] + bof[c0],     co[2 * ks][3] + bof[c0 + 1]);
            cf2[ks][2] = packh2(co[2 * ks + 1][0] + bof[c0 + 8], co[2 * ks + 1][1] + bof[c0 + 9]);
            cf2[ks][3] = packh2(co[2 * ks + 1][2] + bof[c0 + 8], co[2 * ks + 1][3] + bof[c0 + 9]);
        }

        float ya[8][4];
        #pragma unroll
        for (int g = 0; g < 8; ++g)
            #pragma unroll
            for (int j = 0; j < 4; ++j) ya[g][j] = 0.f;
        #pragma unroll
        for (int ks = 0; ks < 4; ++ks) {
            u32 ax[4];
            ldm4(ax, sb + EP_X + aSel + ks * 32);
            #pragma unroll
            for (int g = 0; g < 4; ++g) {
                u32 bw[4];
                ldm4(bw, sb + EP_WLT + (u32)(g * 2304) + bSel + ks * 32);
                mma_f16(ya[2 * g],     ax, bw[0], bw[2]);
                mma_f16(ya[2 * g + 1], ax, bw[1], bw[3]);
            }
        }
        #pragma unroll
        for (int ks = 0; ks < 4; ++ks) {
            #pragma unroll
            for (int g = 0; g < 4; ++g) {
                u32 bw[4];
                ldm4(bw, sb + EP_WLB + (u32)(g * 2304) + bSel + ks * 32);
                mma_f16(ya[2 * g],     cf2[ks], bw[0], bw[2]);
                mma_f16(ya[2 * g + 1], cf2[ks], bw[1], bw[3]);
            }
        }

        const size_t yrA = (size_t)(b * N_ + r0 + w * 16 + rowA) * D_;
        const size_t yrB = yrA + (size_t)8 * D_;
        #pragma unroll
        for (int g = 0; g < 8; ++g) {
            const int C = g * 8 + colq;
            const float b0 = blf[C], b1 = blf[C + 1];
            *(float2*)&y[yrA + C] = make_float2(fmaxf(ya[g][0] + b0, 0.f),
                                                fmaxf(ya[g][1] + b1, 0.f));
            *(float2*)&y[yrB + C] = make_float2(fmaxf(ya[g][2] + b0, 0.f),
                                                fmaxf(ya[g][3] + b1, 0.f));
        }
    }
    __syncthreads();   // epilogue smem reads done before buffers reused

    // prologue: async-load K tile 0 for phase 2
    {
        for (int it = 0; it < 4; ++it) {
            int idx = tid + it * 256;
            int r = idx >> 3, c = idx & 7;
            cpa16(sb + SM_BUF + r * 144 + c * 16,
                  &g_k[kgbase + (size_t)r * D_ + c * 8]);
        }
        CP_COMMIT();
    }

    // =================== Phase 2: S recompute -> attn = h/L =================
    for (int mt = 0; mt < 16; ++mt) {
        CP_WAIT0();
        __syncthreads();
        if (mt < 15) {
            const int m1 = (mt + 1) * 128;
            const u32 nb = sb + SM_BUF + ((mt + 1) & 1) * BUF_SZ;
            for (int it = 0; it < 4; ++it) {
                int idx = tid + it * 256;
                int r = idx >> 3, c = idx & 7;
                cpa16(nb + r * 144 + c * 16,
                      &g_k[kgbase + (size_t)(m1 + r) * D_ + c * 8]);
            }
            CP_COMMIT();
        }

        const u32 sbK = sb + SM_BUF + (mt & 1) * BUF_SZ;
        const int m0 = mt * 128;
        const uint2 mk = maskS[mt * 256 + tid];

        #pragma unroll
        for (int kk = 0; kk < 8; ++kk) {
            float acc[2][4];
            #pragma unroll
            for (int j = 0; j < 4; ++j) { acc[0][j] = 0.f; acc[1][j] = 0.f; }
            #pragma unroll
            for (int ks = 0; ks < 4; ++ks) {
                u32 bh[4];
                ldm4(bh, sbK + (u32)(kk * 2304) + bSel + ks * 32);
                mma_f16(acc[0], qa[ks], bh[0], bh[2]);
                mma_f16(acc[1], qa[ks], bh[1], bh[3]);
            }
            const u32 byte = ((kk < 4) ? mk.x >> (kk * 8) : mk.y >> ((kk - 4) * 8)) & 0xffu;
            const int C0 = kk * 16 + colq;
            float p00 = (byte & 0x01u) ? ex2(acc[0][0]) * iL0 : 0.f;
            float p01 = (byte & 0x02u) ? ex2(acc[0][1]) * iL0 : 0.f;
            float p02 = (byte & 0x04u) ? ex2(acc[0][2]) * iL1 : 0.f;
            float p03 = (byte & 0x08u) ? ex2(acc[0][3]) * iL1 : 0.f;
            float p10 = (byte & 0x10u) ? ex2(acc[1][0]) * iL0 : 0.f;
            float p11 = (byte & 0x20u) ? ex2(acc[1][1]) * iL0 : 0.f;
            float p12 = (byte & 0x40u) ? ex2(acc[1][2]) * iL1 : 0.f;
            float p13 = (byte & 0x80u) ? ex2(acc[1][3]) * iL1 : 0.f;
            *(float2*)&attn[growA + m0 + C0]     = make_float2(p00, p01);
            *(float2*)&attn[growA + m0 + C0 + 8] = make_float2(p10, p11);
            *(float2*)&attn[growB + m0 + C0]     = make_float2(p02, p03);
            *(float2*)&attn[growB + m0 + C0 + 8] = make_float2(p12, p13);
        }
    }
}

// ============================================================================
extern "C" void kernel_launch(void* const* d_in, const int* in_sizes, int n_in,
                              void* d_out, int out_size)
{
    const float* x   = (const float*)d_in[0];
    const int*   adj = (const int*)  d_in[1];
    const float* Wq  = (const float*)d_in[2];
    const float* bq  = (const float*)d_in[3];
    const float* Wk  = (const float*)d_in[4];
    const float* bk  = (const float*)d_in[5];
    const float* Wv  = (const float*)d_in[6];
    const float* bv  = (const float*)d_in[7];
    const float* Wo  = (const float*)d_in[8];
    const float* bo  = (const float*)d_in[9];
    const float* Wl  = (const float*)d_in[10];
    const float* bl  = (const float*)d_in[11];

    float* y    = (float*)d_out;                         // [B,N,D]
    float* attn = (float*)d_out + (size_t)B_ * N_ * D_;  // [B,N,N]

    cudaFuncSetAttribute(proj_qkv,
                         cudaFuncAttributeMaxDynamicSharedMemorySize,
                         PROJ_SMEM_BYTES);
    cudaFuncSetAttribute(attn_kernel,
                         cudaFuncAttributeMaxDynamicSharedMemorySize,
                         ATTN_SMEM);

    proj_qkv<<<dim3(16, 16), 256, PROJ_SMEM_BYTES>>>(x, Wq, bq, Wk, bk, Wv, bv);
    attn_kernel<<<dim3(16, 16), 256, ATTN_SMEM>>>(adj, x, Wo, bo, Wl, bl, y, attn);
}